// round 13
// baseline (speedup 1.0000x reference)
#include <cuda_runtime.h>
#include <cuda_bf16.h>
#include <mma.h>

using namespace nvcuda;

#define N_NODES  100000
#define N_EDGES  600000
#define N_GRAPHS 256
#define HID      128
#define IN_DIM   7
#define BN_EPS   1e-5f
#define NB_SCAN  ((N_NODES + 255) / 256)   // 391 scan blocks
#define N_PAD    (N_NODES + 128)           // row padding for full-tile wmma I/O
#define FG_SMEM  ((128 * 132 + 32 * 132) * 4)   // As + Bs = 84480 bytes

// ---------------- scratch (static device globals; no allocs allowed) --------
__device__ float g_buf0[N_PAD * HID];     // hl ping buffer
__device__ float g_buf1[N_PAD * HID];     // hl pong buffer
__device__ float g_Wc[2][HID * HID];      // tf32-rounded W1, W2
__device__ float g_dinv[N_NODES];         // rsqrt(deg+1)
__device__ float g_pool[N_GRAPHS * HID];
__device__ float g_cnt[N_GRAPHS];
__device__ float g_p[64];                 // pocket embedding
__device__ float g_bns[3][HID];           // BN scale  = gamma * rsqrt(var+eps)
__device__ float g_bnb[3][HID];           // BN shift  = beta - mean*scale
// CSR scratch
__device__ int   g_cnti[NB_SCAN * 256];   // per-node in-degree, then fill cursor
__device__ int   g_rowptr[N_NODES + 1];
__device__ int   g_ecol[N_EDGES];         // src node per CSR slot
__device__ int   g_bsum[512];             // per-block scan sums

// ---------------- merged prep: BN fold + pocket MLP (1 block, 384 thr) ------
__global__ void k_prep(const float* __restrict__ gamma, const float* __restrict__ beta,
                       const float* __restrict__ mean,  const float* __restrict__ var,
                       const float* __restrict__ pocket,
                       const float* __restrict__ pw1, const float* __restrict__ pb1,
                       const float* __restrict__ pw2, const float* __restrict__ pb2) {
    __shared__ float t[64];
    int j = threadIdx.x;
    if (j < 3 * HID) {
        float s = gamma[j] * rsqrtf(var[j] + BN_EPS);
        ((float*)g_bns)[j] = s;
        ((float*)g_bnb)[j] = beta[j] - mean[j] * s;
    }
    if (j < 64) {
        float a = pb1[j];
        #pragma unroll
        for (int k = 0; k < 28; ++k) a = fmaf(pocket[k], pw1[k * 64 + j], a);
        t[j] = fmaxf(a, 0.0f);
    }
    __syncthreads();
    if (j < 64) {
        float b = pb2[j];
        #pragma unroll
        for (int k = 0; k < 64; ++k) b = fmaf(t[k], pw2[k * 64 + j], b);
        g_p[j] = b;
    }
}

// zero counters/pool + tf32-round W1,W2 (merged elementwise prep)
__global__ void k_zeroW(const float* __restrict__ W1, const float* __restrict__ W2) {
    int i = blockIdx.x * blockDim.x + threadIdx.x;
    if (i < NB_SCAN * 256) g_cnti[i] = 0;
    if (i < N_GRAPHS * HID) g_pool[i] = 0.0f;
    if (i < N_GRAPHS) g_cnt[i] = 0.0f;
    if (i < HID * HID) {
        g_Wc[0][i] = wmma::__float_to_tf32(W1[i]);
        g_Wc[1][i] = wmma::__float_to_tf32(W2[i]);
    }
}

__global__ void k_count(const int* __restrict__ dst) {
    int i = blockIdx.x * blockDim.x + threadIdx.x;
    if (i < N_EDGES) atomicAdd(&g_cnti[dst[i]], 1);
}

// per-block inclusive scan of g_cnti -> g_rowptr (block-local), totals -> g_bsum
// also computes dinv = rsqrt(deg+1)
__global__ void k_scan1() {
    __shared__ int s[256];
    int t = threadIdx.x;
    int i = blockIdx.x * 256 + t;
    int v = (i < N_NODES) ? g_cnti[i] : 0;
    if (i < N_NODES) g_dinv[i] = rsqrtf((float)v + 1.0f);
    s[t] = v;
    __syncthreads();
    #pragma unroll
    for (int d = 1; d < 256; d <<= 1) {
        int x = (t >= d) ? s[t - d] : 0;
        __syncthreads();
        if (t >= d) s[t] += x;
        __syncthreads();
    }
    if (i <= N_NODES) g_rowptr[i] = s[t];     // inclusive, block-local
    if (t == 255) g_bsum[blockIdx.x] = s[255];
}

__global__ void k_scan2() {
    __shared__ int s[512];
    int t = threadIdx.x;
    int v = (t < NB_SCAN) ? g_bsum[t] : 0;
    s[t] = v;
    __syncthreads();
    #pragma unroll
    for (int d = 1; d < 512; d <<= 1) {
        int x = (t >= d) ? s[t - d] : 0;
        __syncthreads();
        if (t >= d) s[t] += x;
        __syncthreads();
    }
    if (t < NB_SCAN) g_bsum[t] = s[t] - v;    // exclusive block offset
}

__global__ void k_scan3() {
    int i = blockIdx.x * blockDim.x + threadIdx.x;
    if (i < N_NODES) {
        int incl = g_rowptr[i];
        int cnt  = g_cnti[i];
        g_rowptr[i] = g_bsum[i >> 8] + incl - cnt;   // global exclusive
        g_cnti[i] = 0;
    }
    if (i == 0) g_rowptr[N_NODES] = N_EDGES;
}

__global__ void k_fill(const int* __restrict__ src, const int* __restrict__ dst) {
    int e = blockIdx.x * blockDim.x + threadIdx.x;
    if (e < N_EDGES) {
        int d = dst[e];
        int pos = g_rowptr[d] + atomicAdd(&g_cnti[d], 1);
        g_ecol[pos] = src[e];
    }
}

// ---------------- layer 0 GEMM: x[N,7] @ W0[7,128] -> g_buf1 (hl only) ------
__global__ void k_gemm0(const float* __restrict__ x, const float* __restrict__ W0) {
    __shared__ float Ws[IN_DIM * HID];
    int tid = threadIdx.x;
    for (int i = tid; i < IN_DIM * HID; i += 256) Ws[i] = W0[i];
    __syncthreads();

    int node = blockIdx.x * 8 + (tid >> 5);
    int col  = (tid & 31) * 4;
    if (node >= N_NODES) return;

    float xr[IN_DIM];
    #pragma unroll
    for (int i = 0; i < IN_DIM; ++i) xr[i] = __ldg(&x[node * IN_DIM + i]);

    float4 acc = make_float4(0.f, 0.f, 0.f, 0.f);
    #pragma unroll
    for (int i = 0; i < IN_DIM; ++i) {
        float4 w = *(const float4*)&Ws[i * HID + col];
        acc.x = fmaf(xr[i], w.x, acc.x);
        acc.y = fmaf(xr[i], w.y, acc.y);
        acc.z = fmaf(xr[i], w.z, acc.z);
        acc.w = fmaf(xr[i], w.w, acc.w);
    }
    *(float4*)(g_buf1 + node * HID + col) = acc;
}

// ---------------- fused gather + GEMM --------------------------------------
// Phase 1 (gather into smem): for each tile row r (node), A[r] =
//   tf32( relu( BN[bn]( (sum_s hl_in[s]*dinv[s] + hl_in[node]*dinv[node]) * dinv[node] + bias ) ) )
// Phase 2: hl_out = A @ Wc[widx]  (wmma tf32).  dir: 0 = buf1->buf0, 1 = buf0->buf1.
// Intermediate agg NEVER touches gmem.
__global__ void __launch_bounds__(256, 2)
k_fgemm(int widx, const float* __restrict__ bias, int bn_idx, int dir) {
    extern __shared__ float smem[];
    float (*As)[132] = (float(*)[132])smem;                 // 128 x 132
    float (*Bs)[132] = (float(*)[132])(smem + 128 * 132);   // 32 x 132

    const float* in  = dir ? g_buf0 : g_buf1;
    float*       out = dir ? g_buf1 : g_buf0;
    const float* Wc  = g_Wc[widx];

    int tid = threadIdx.x;
    int wid = tid >> 5, lane = tid & 31;
    int warp_m = wid >> 1, warp_n = wid & 1;
    int row0 = blockIdx.x * 128;

    // --- Phase 1: gather 16 rows per warp ---
    float4 sc = ((const float4*)g_bns[bn_idx])[lane];
    float4 sh = ((const float4*)g_bnb[bn_idx])[lane];
    float4 b4 = ((const float4*)bias)[lane];
    for (int rr = 0; rr < 16; ++rr) {
        int r = wid * 16 + rr;
        int node = row0 + r;
        float4 res = make_float4(0.f, 0.f, 0.f, 0.f);
        if (node < N_NODES) {
            int beg = g_rowptr[node];
            int end = g_rowptr[node + 1];
            float4 acc = make_float4(0.f, 0.f, 0.f, 0.f);
            for (int e = beg; e < end; ++e) {
                int s = g_ecol[e];                    // warp-uniform -> broadcast
                float ds = g_dinv[s];
                float4 v = ((const float4*)in)[s * 32 + lane];
                acc.x = fmaf(v.x, ds, acc.x);
                acc.y = fmaf(v.y, ds, acc.y);
                acc.z = fmaf(v.z, ds, acc.z);
                acc.w = fmaf(v.w, ds, acc.w);
            }
            float dd = g_dinv[node];
            float4 hv = ((const float4*)in)[node * 32 + lane];   // self-loop
            acc.x = fmaf(hv.x, dd, acc.x);
            acc.y = fmaf(hv.y, dd, acc.y);
            acc.z = fmaf(hv.z, dd, acc.z);
            acc.w = fmaf(hv.w, dd, acc.w);
            res.x = fmaf(acc.x, dd, b4.x);
            res.y = fmaf(acc.y, dd, b4.y);
            res.z = fmaf(acc.z, dd, b4.z);
            res.w = fmaf(acc.w, dd, b4.w);
            res.x = wmma::__float_to_tf32(fmaxf(fmaf(res.x, sc.x, sh.x), 0.f));
            res.y = wmma::__float_to_tf32(fmaxf(fmaf(res.y, sc.y, sh.y), 0.f));
            res.z = wmma::__float_to_tf32(fmaxf(fmaf(res.z, sc.z, sh.z), 0.f));
            res.w = wmma::__float_to_tf32(fmaxf(fmaf(res.w, sc.w, sh.w), 0.f));
        }
        *(float4*)&As[r][lane * 4] = res;
    }
    __syncthreads();

    // --- Phase 2: wmma mainloop ---
    wmma::fragment<wmma::accumulator, 16, 16, 8, float> acc[2][4];
    #pragma unroll
    for (int mt = 0; mt < 2; ++mt)
        #pragma unroll
        for (int nt = 0; nt < 4; ++nt) wmma::fill_fragment(acc[mt][nt], 0.0f);

    for (int k0 = 0; k0 < HID; k0 += 32) {
        #pragma unroll
        for (int i = 0; i < 4; ++i) {
            int f = tid + 256 * i;
            int r = f >> 5, c = (f & 31) * 4;
            *(float4*)&Bs[r][c] = *(const float4*)(Wc + (k0 + r) * HID + c);
        }
        __syncthreads();

        #pragma unroll
        for (int kk = 0; kk < 4; ++kk) {
            wmma::fragment<wmma::matrix_a, 16, 16, 8, wmma::precision::tf32, wmma::row_major> fa[2];
            #pragma unroll
            for (int mt = 0; mt < 2; ++mt)
                wmma::load_matrix_sync(fa[mt], &As[warp_m * 32 + mt * 16][k0 + kk * 8], 132);
            #pragma unroll
            for (int nt = 0; nt < 4; ++nt) {
                wmma::fragment<wmma::matrix_b, 16, 16, 8, wmma::precision::tf32, wmma::row_major> fb;
                wmma::load_matrix_sync(fb, &Bs[kk * 8][warp_n * 64 + nt * 16], 132);
                wmma::mma_sync(acc[0][nt], fa[0], fb, acc[0][nt]);
                wmma::mma_sync(acc[1][nt], fa[1], fb, acc[1][nt]);
            }
        }
        __syncthreads();
    }

    #pragma unroll
    for (int mt = 0; mt < 2; ++mt) {
        int row = row0 + warp_m * 32 + mt * 16;
        #pragma unroll
        for (int nt = 0; nt < 4; ++nt) {
            int col = warp_n * 64 + nt * 16;
            wmma::store_matrix_sync(out + row * HID + col, acc[mt][nt], HID, wmma::mem_row_major);
        }
    }
}

// ---------------- fused gather + BN2 + ReLU + pooling -----------------------
__global__ void k_poolg(const float* __restrict__ bias, const int* __restrict__ batch) {
    int node = blockIdx.x * 8 + (threadIdx.x >> 5);
    if (node >= N_NODES) return;
    int l = threadIdx.x & 31;

    const float* in = g_buf1;   // hl2 lives in buf1 (dir=1 on second fgemm)
    int beg = g_rowptr[node];
    int end = g_rowptr[node + 1];
    float4 acc = make_float4(0.f, 0.f, 0.f, 0.f);
    for (int e = beg; e < end; ++e) {
        int s = g_ecol[e];
        float ds = g_dinv[s];
        float4 v = ((const float4*)in)[s * 32 + l];
        acc.x = fmaf(v.x, ds, acc.x);
        acc.y = fmaf(v.y, ds, acc.y);
        acc.z = fmaf(v.z, ds, acc.z);
        acc.w = fmaf(v.w, ds, acc.w);
    }
    float dd = g_dinv[node];
    float4 hv = ((const float4*)in)[node * 32 + l];
    acc.x = fmaf(hv.x, dd, acc.x);
    acc.y = fmaf(hv.y, dd, acc.y);
    acc.z = fmaf(hv.z, dd, acc.z);
    acc.w = fmaf(hv.w, dd, acc.w);
    float4 b4 = ((const float4*)bias)[l];
    float4 r = make_float4(fmaf(acc.x, dd, b4.x), fmaf(acc.y, dd, b4.y),
                           fmaf(acc.z, dd, b4.z), fmaf(acc.w, dd, b4.w));
    float4 sc = ((const float4*)g_bns[2])[l];
    float4 sh = ((const float4*)g_bnb[2])[l];
    r.x = fmaxf(fmaf(r.x, sc.x, sh.x), 0.f);
    r.y = fmaxf(fmaf(r.y, sc.y, sh.y), 0.f);
    r.z = fmaxf(fmaf(r.z, sc.z, sh.z), 0.f);
    r.w = fmaxf(fmaf(r.w, sc.w, sh.w), 0.f);

    int b = batch[node];
    float* p = g_pool + b * HID + l * 4;
    asm volatile("red.global.add.v4.f32 [%0], {%1, %2, %3, %4};"
                 :: "l"(p), "f"(r.x), "f"(r.y), "f"(r.z), "f"(r.w) : "memory");
    if (l == 0) atomicAdd(&g_cnt[b], 1.0f);
}

// ---------------- head: mean, concat pocket, 192->96 relu ->1 ---------------
__global__ void k_head(const float* __restrict__ cw1, const float* __restrict__ cb1,
                       const float* __restrict__ cw2, const float* __restrict__ cb2,
                       float* __restrict__ out) {
    __shared__ float emb[192];
    __shared__ float hid[96];
    int g = blockIdx.x;
    int j = threadIdx.x;
    float inv = 1.0f / fmaxf(g_cnt[g], 1.0f);
    for (int idx = j; idx < 192; idx += 96)
        emb[idx] = (idx < HID) ? g_pool[g * HID + idx] * inv : g_p[idx - HID];
    __syncthreads();
    float a = cb1[j];
    #pragma unroll 8
    for (int k = 0; k < 192; ++k) a = fmaf(emb[k], cw1[k * 96 + j], a);
    hid[j] = fmaxf(a, 0.0f) * cw2[j];
    __syncthreads();
    if (j == 0) {
        float s = cb2[0];
        #pragma unroll
        for (int k = 0; k < 96; ++k) s += hid[k];
        out[g] = s;
    }
}

// ---------------- launch --------------------------------------------------
extern "C" void kernel_launch(void* const* d_in, const int* in_sizes, int n_in,
                              void* d_out, int out_size) {
    const float* x      = (const float*)d_in[0];
    const int*   ei     = (const int*)  d_in[1];
    const int*   src    = ei;
    const int*   dst    = ei + N_EDGES;
    const int*   batch  = (const int*)  d_in[2];
    const float* pocket = (const float*)d_in[3];
    const float* W0 = (const float*)d_in[4];  const float* b0 = (const float*)d_in[5];
    const float* W1 = (const float*)d_in[6];  const float* b1 = (const float*)d_in[7];
    const float* W2 = (const float*)d_in[8];  const float* b2 = (const float*)d_in[9];
    const float* bn_gamma = (const float*)d_in[10];
    const float* bn_beta  = (const float*)d_in[11];
    const float* bn_mean  = (const float*)d_in[12];
    const float* bn_var   = (const float*)d_in[13];
    const float* pw1 = (const float*)d_in[14]; const float* pb1 = (const float*)d_in[15];
    const float* pw2 = (const float*)d_in[16]; const float* pb2 = (const float*)d_in[17];
    const float* cw1 = (const float*)d_in[18]; const float* cb1 = (const float*)d_in[19];
    const float* cw2 = (const float*)d_in[20]; const float* cb2 = (const float*)d_in[21];
    float* out = (float*)d_out;

    // opt into 84.5KB dynamic smem for the fused GEMM (attribute set, not an alloc)
    cudaFuncSetAttribute(k_fgemm, cudaFuncAttributeMaxDynamicSharedMemorySize, FG_SMEM);

    // prep + CSR build
    k_prep<<<1, 384>>>(bn_gamma, bn_beta, bn_mean, bn_var,
                       pocket, pw1, pb1, pw2, pb2);
    k_zeroW<<<NB_SCAN, 256>>>(W1, W2);
    k_count<<<(N_EDGES + 255) / 256, 256>>>(dst);
    k_scan1<<<NB_SCAN, 256>>>();
    k_scan2<<<1, 512>>>();
    k_scan3<<<NB_SCAN, 256>>>();
    k_fill<<<(N_EDGES + 255) / 256, 256>>>(src, dst);

    int tc_grid = (N_NODES + 127) / 128;          // 782 tiles
    int node_warp_grid = (N_NODES + 7) / 8;

    // layer 0: hl0 -> buf1
    k_gemm0<<<node_warp_grid, 256>>>(x, W0);
    // layer 1: gather(buf1)+BN0+ReLU -> GEMM W1 -> buf0
    k_fgemm<<<tc_grid, 256, FG_SMEM>>>(0, b0, 0, 0);
    // layer 2: gather(buf0)+BN1+ReLU -> GEMM W2 -> buf1
    k_fgemm<<<tc_grid, 256, FG_SMEM>>>(1, b1, 1, 1);
    // gather(buf1)+BN2+ReLU -> pool
    k_poolg<<<node_warp_grid, 256>>>(b2, batch);
    k_head<<<N_GRAPHS, 96>>>(cw1, cb1, cw2, cb2, out);
}

// round 14
// speedup vs baseline: 1.0749x; 1.0749x over previous
#include <cuda_runtime.h>
#include <cuda_bf16.h>
#include <mma.h>

using namespace nvcuda;

#define N_NODES  100000
#define N_EDGES  600000
#define N_GRAPHS 256
#define HID      128
#define IN_DIM   7
#define BN_EPS   1e-5f
#define NB_SCAN  ((N_NODES + 255) / 256)   // 391 scan blocks
#define N_PAD    (N_NODES + 128)           // row padding for full-tile wmma I/O

// ---------------- scratch (static device globals; no allocs allowed) --------
__device__ float g_buf0[N_PAD * HID];     // h buffer (gather out, post BN+ReLU)
__device__ float g_buf1[N_PAD * HID];     // hl' buffer (GEMM out, pre-scaled by dinv)
__device__ float g_Wc[2][HID * HID];      // tf32-rounded W1, W2
__device__ float g_dinv[N_NODES];         // rsqrt(deg+1)
__device__ float g_pool[N_GRAPHS * HID];
__device__ float g_cnt[N_GRAPHS];
__device__ float g_p[64];                 // pocket embedding
__device__ float g_bns[3][HID];           // BN scale  = gamma * rsqrt(var+eps)
__device__ float g_bnb[3][HID];           // BN shift  = beta - mean*scale
// CSR scratch
__device__ int   g_cnti[NB_SCAN * 256];   // per-node in-degree, then fill cursor
__device__ int   g_rowptr[N_NODES + 1];
__device__ int   g_ecol[N_EDGES];         // src node per CSR slot
__device__ int   g_bsum[512];             // per-block scan sums

// ---------------- merged prep: BN fold + pocket MLP (1 block, 384 thr) ------
__global__ void k_prep(const float* __restrict__ gamma, const float* __restrict__ beta,
                       const float* __restrict__ mean,  const float* __restrict__ var,
                       const float* __restrict__ pocket,
                       const float* __restrict__ pw1, const float* __restrict__ pb1,
                       const float* __restrict__ pw2, const float* __restrict__ pb2) {
    __shared__ float t[64];
    int j = threadIdx.x;
    if (j < 3 * HID) {
        float s = gamma[j] * rsqrtf(var[j] + BN_EPS);
        ((float*)g_bns)[j] = s;
        ((float*)g_bnb)[j] = beta[j] - mean[j] * s;
    }
    if (j < 64) {
        float a = pb1[j];
        #pragma unroll
        for (int k = 0; k < 28; ++k) a = fmaf(pocket[k], pw1[k * 64 + j], a);
        t[j] = fmaxf(a, 0.0f);
    }
    __syncthreads();
    if (j < 64) {
        float b = pb2[j];
        #pragma unroll
        for (int k = 0; k < 64; ++k) b = fmaf(t[k], pw2[k * 64 + j], b);
        g_p[j] = b;
    }
}

// zero counters/pool + tf32-round W1,W2 (merged elementwise prep)
__global__ void k_zeroW(const float* __restrict__ W1, const float* __restrict__ W2) {
    int i = blockIdx.x * blockDim.x + threadIdx.x;
    if (i < NB_SCAN * 256) g_cnti[i] = 0;
    if (i < N_GRAPHS * HID) g_pool[i] = 0.0f;
    if (i < N_GRAPHS) g_cnt[i] = 0.0f;
    if (i < HID * HID) {
        g_Wc[0][i] = wmma::__float_to_tf32(W1[i]);
        g_Wc[1][i] = wmma::__float_to_tf32(W2[i]);
    }
}

__global__ void k_count(const int* __restrict__ dst) {
    int i = blockIdx.x * blockDim.x + threadIdx.x;
    if (i < N_EDGES) atomicAdd(&g_cnti[dst[i]], 1);
}

// per-block inclusive scan of g_cnti -> g_rowptr (block-local), totals -> g_bsum
// also computes dinv = rsqrt(deg+1)
__global__ void k_scan1() {
    __shared__ int s[256];
    int t = threadIdx.x;
    int i = blockIdx.x * 256 + t;
    int v = (i < N_NODES) ? g_cnti[i] : 0;
    if (i < N_NODES) g_dinv[i] = rsqrtf((float)v + 1.0f);
    s[t] = v;
    __syncthreads();
    #pragma unroll
    for (int d = 1; d < 256; d <<= 1) {
        int x = (t >= d) ? s[t - d] : 0;
        __syncthreads();
        if (t >= d) s[t] += x;
        __syncthreads();
    }
    if (i <= N_NODES) g_rowptr[i] = s[t];     // inclusive, block-local
    if (t == 255) g_bsum[blockIdx.x] = s[255];
}

__global__ void k_scan2() {
    __shared__ int s[512];
    int t = threadIdx.x;
    int v = (t < NB_SCAN) ? g_bsum[t] : 0;
    s[t] = v;
    __syncthreads();
    #pragma unroll
    for (int d = 1; d < 512; d <<= 1) {
        int x = (t >= d) ? s[t - d] : 0;
        __syncthreads();
        if (t >= d) s[t] += x;
        __syncthreads();
    }
    if (t < NB_SCAN) g_bsum[t] = s[t] - v;    // exclusive block offset
}

__global__ void k_scan3() {
    int i = blockIdx.x * blockDim.x + threadIdx.x;
    if (i < N_NODES) {
        int incl = g_rowptr[i];
        int cnt  = g_cnti[i];
        g_rowptr[i] = g_bsum[i >> 8] + incl - cnt;   // global exclusive
        g_cnti[i] = 0;
    }
    if (i == 0) g_rowptr[N_NODES] = N_EDGES;
}

__global__ void k_fill(const int* __restrict__ src, const int* __restrict__ dst) {
    int e = blockIdx.x * blockDim.x + threadIdx.x;
    if (e < N_EDGES) {
        int d = dst[e];
        int pos = g_rowptr[d] + atomicAdd(&g_cnti[d], 1);
        g_ecol[pos] = src[e];
    }
}

// ---------------- layer 0: hl0' = (x @ W0) * dinv  -> g_buf1 ----------------
__global__ void k_gemm0(const float* __restrict__ x, const float* __restrict__ W0) {
    __shared__ float Ws[IN_DIM * HID];
    int tid = threadIdx.x;
    for (int i = tid; i < IN_DIM * HID; i += 256) Ws[i] = W0[i];
    __syncthreads();

    int node = blockIdx.x * 8 + (tid >> 5);
    int col  = (tid & 31) * 4;
    if (node >= N_NODES) return;

    float xr[IN_DIM];
    #pragma unroll
    for (int i = 0; i < IN_DIM; ++i) xr[i] = __ldg(&x[node * IN_DIM + i]);

    float4 acc = make_float4(0.f, 0.f, 0.f, 0.f);
    #pragma unroll
    for (int i = 0; i < IN_DIM; ++i) {
        float4 w = *(const float4*)&Ws[i * HID + col];
        acc.x = fmaf(xr[i], w.x, acc.x);
        acc.y = fmaf(xr[i], w.y, acc.y);
        acc.z = fmaf(xr[i], w.z, acc.z);
        acc.w = fmaf(xr[i], w.w, acc.w);
    }
    float dv = g_dinv[node];
    acc.x *= dv; acc.y *= dv; acc.z *= dv; acc.w *= dv;
    *(float4*)(g_buf1 + node * HID + col) = acc;
}

// ---------------- wmma tf32 GEMM: buf0 (h) @ Wc[widx] * dinv -> buf1 --------
// Epilogue stages acc through As and scales each output row by dinv[row]
// (pre-scaling hl so the gather inner loop is pure adds).
__global__ void __launch_bounds__(256, 2)
k_gemm128_tc(int widx) {
    __shared__ float As[128][36];    // [m][k] in mainloop; reused [m][n-chunk] staging? no: staging uses Bs too
    __shared__ float Bs[32][132];    // [k][n]

    const float* Wc = g_Wc[widx];
    int tid = threadIdx.x;
    int wid = tid >> 5;
    int warp_m = wid >> 1, warp_n = wid & 1;
    int row0 = blockIdx.x * 128;

    wmma::fragment<wmma::accumulator, 16, 16, 8, float> acc[2][4];
    #pragma unroll
    for (int mt = 0; mt < 2; ++mt)
        #pragma unroll
        for (int nt = 0; nt < 4; ++nt) wmma::fill_fragment(acc[mt][nt], 0.0f);

    for (int k0 = 0; k0 < HID; k0 += 32) {
        #pragma unroll
        for (int i = 0; i < 4; ++i) {
            int f = tid + 256 * i;
            int r = f >> 5, c = (f & 31) * 4;
            *(float4*)&Bs[r][c] = *(const float4*)(Wc + (k0 + r) * HID + c);
        }
        #pragma unroll
        for (int i = 0; i < 4; ++i) {
            int f = tid + 256 * i;
            int r = f >> 3, c4 = (f & 7) * 4;
            *(float4*)&As[r][c4] = *(const float4*)(g_buf0 + (row0 + r) * HID + k0 + c4);
        }
        __syncthreads();

        #pragma unroll
        for (int kk = 0; kk < 4; ++kk) {
            wmma::fragment<wmma::matrix_a, 16, 16, 8, wmma::precision::tf32, wmma::row_major> fa[2];
            #pragma unroll
            for (int mt = 0; mt < 2; ++mt)
                wmma::load_matrix_sync(fa[mt], &As[warp_m * 32 + mt * 16][kk * 8], 36);
            #pragma unroll
            for (int nt = 0; nt < 4; ++nt) {
                wmma::fragment<wmma::matrix_b, 16, 16, 8, wmma::precision::tf32, wmma::row_major> fb;
                wmma::load_matrix_sync(fb, &Bs[kk * 8][warp_n * 64 + nt * 16], 132);
                wmma::mma_sync(acc[0][nt], fa[0], fb, acc[0][nt]);
                wmma::mma_sync(acc[1][nt], fa[1], fb, acc[1][nt]);
            }
        }
        __syncthreads();
    }

    // ---- epilogue: stage 64-col halves through Bs-sized smem, scale by dinv ----
    // Each warp owns 32 rows x 64 cols; stage via a 128x68 view over As+Bs? Simpler:
    // two passes of 128x64 through a [128][68] region carved from As/Bs jointly.
    // As(128*36) + Bs(32*132) = 8832 floats >= 128*68=8704.
    float* stage = &As[0][0];            // contiguous smem start, 128*68 floats
    const int SLD = 68;
    #pragma unroll
    for (int half = 0; half < 2; ++half) {
        // warps with warp_n == half write their acc tiles into stage
        if (warp_n == half) {
            #pragma unroll
            for (int mt = 0; mt < 2; ++mt) {
                int r = warp_m * 32 + mt * 16;
                #pragma unroll
                for (int nt = 0; nt < 4; ++nt)
                    wmma::store_matrix_sync(stage + r * SLD + nt * 16, acc[mt][nt], SLD, wmma::mem_row_major);
            }
        }
        __syncthreads();
        // all 256 threads scale+write 128x64 floats (= 2048 float4)
        #pragma unroll
        for (int i = 0; i < 8; ++i) {
            int f = tid + 256 * i;
            int r = f >> 4, c4 = (f & 15) * 4;
            int row = row0 + r;
            float dv = (row < N_NODES) ? g_dinv[row] : 0.f;
            float4 v = *(float4*)(stage + r * SLD + c4);
            v.x *= dv; v.y *= dv; v.z *= dv; v.w *= dv;
            *(float4*)(g_buf1 + row * HID + half * 64 + c4) = v;
        }
        __syncthreads();
    }
}

// ---------------- CSR gather (pure-add inner loop, unroll x4) ----------------
// h = relu(BN[bn]( (Σ hl'[s] + hl'[d]) * dinv[d] + bias )); optional tf32 round.
// in = g_buf1 (pre-scaled hl'), out = g_buf0.
__global__ void k_gather(const float* __restrict__ bias, int bn_idx, int do_round) {
    int node = blockIdx.x * 8 + (threadIdx.x >> 5);
    if (node >= N_NODES) return;
    int l = threadIdx.x & 31;

    const float4* in = (const float4*)g_buf1;
    int beg = g_rowptr[node];
    int end = g_rowptr[node + 1];

    float4 a0 = in[node * 32 + l];          // self-loop term hl'[d]
    float4 a1 = make_float4(0.f, 0.f, 0.f, 0.f);
    float4 a2 = make_float4(0.f, 0.f, 0.f, 0.f);
    float4 a3 = make_float4(0.f, 0.f, 0.f, 0.f);

    int e = beg;
    for (; e + 4 <= end; e += 4) {
        int s0 = g_ecol[e], s1 = g_ecol[e + 1], s2 = g_ecol[e + 2], s3 = g_ecol[e + 3];
        float4 v0 = in[s0 * 32 + l];
        float4 v1 = in[s1 * 32 + l];
        float4 v2 = in[s2 * 32 + l];
        float4 v3 = in[s3 * 32 + l];
        a0.x += v0.x; a0.y += v0.y; a0.z += v0.z; a0.w += v0.w;
        a1.x += v1.x; a1.y += v1.y; a1.z += v1.z; a1.w += v1.w;
        a2.x += v2.x; a2.y += v2.y; a2.z += v2.z; a2.w += v2.w;
        a3.x += v3.x; a3.y += v3.y; a3.z += v3.z; a3.w += v3.w;
    }
    for (; e < end; ++e) {
        int s = g_ecol[e];
        float4 v = in[s * 32 + l];
        a0.x += v.x; a0.y += v.y; a0.z += v.z; a0.w += v.w;
    }
    float4 acc = make_float4(a0.x + a1.x + a2.x + a3.x, a0.y + a1.y + a2.y + a3.y,
                             a0.z + a1.z + a2.z + a3.z, a0.w + a1.w + a2.w + a3.w);

    float dd = g_dinv[node];
    float4 b4 = ((const float4*)bias)[l];
    float4 r = make_float4(fmaf(acc.x, dd, b4.x), fmaf(acc.y, dd, b4.y),
                           fmaf(acc.z, dd, b4.z), fmaf(acc.w, dd, b4.w));
    float4 sc = ((const float4*)g_bns[bn_idx])[l];
    float4 sh = ((const float4*)g_bnb[bn_idx])[l];
    r.x = fmaxf(fmaf(r.x, sc.x, sh.x), 0.f);
    r.y = fmaxf(fmaf(r.y, sc.y, sh.y), 0.f);
    r.z = fmaxf(fmaf(r.z, sc.z, sh.z), 0.f);
    r.w = fmaxf(fmaf(r.w, sc.w, sh.w), 0.f);
    if (do_round) {
        r.x = wmma::__float_to_tf32(r.x);
        r.y = wmma::__float_to_tf32(r.y);
        r.z = wmma::__float_to_tf32(r.z);
        r.w = wmma::__float_to_tf32(r.w);
    }
    ((float4*)g_buf0)[node * 32 + l] = r;
}

// ---------------- fused gather + BN2 + ReLU + pooling -----------------------
__global__ void k_poolg(const float* __restrict__ bias, const int* __restrict__ batch) {
    int node = blockIdx.x * 8 + (threadIdx.x >> 5);
    if (node >= N_NODES) return;
    int l = threadIdx.x & 31;

    const float4* in = (const float4*)g_buf1;
    int beg = g_rowptr[node];
    int end = g_rowptr[node + 1];

    float4 a0 = in[node * 32 + l];
    float4 a1 = make_float4(0.f, 0.f, 0.f, 0.f);
    float4 a2 = make_float4(0.f, 0.f, 0.f, 0.f);
    float4 a3 = make_float4(0.f, 0.f, 0.f, 0.f);
    int e = beg;
    for (; e + 4 <= end; e += 4) {
        int s0 = g_ecol[e], s1 = g_ecol[e + 1], s2 = g_ecol[e + 2], s3 = g_ecol[e + 3];
        float4 v0 = in[s0 * 32 + l];
        float4 v1 = in[s1 * 32 + l];
        float4 v2 = in[s2 * 32 + l];
        float4 v3 = in[s3 * 32 + l];
        a0.x += v0.x; a0.y += v0.y; a0.z += v0.z; a0.w += v0.w;
        a1.x += v1.x; a1.y += v1.y; a1.z += v1.z; a1.w += v1.w;
        a2.x += v2.x; a2.y += v2.y; a2.z += v2.z; a2.w += v2.w;
        a3.x += v3.x; a3.y += v3.y; a3.z += v3.z; a3.w += v3.w;
    }
    for (; e < end; ++e) {
        int s = g_ecol[e];
        float4 v = in[s * 32 + l];
        a0.x += v.x; a0.y += v.y; a0.z += v.z; a0.w += v.w;
    }
    float4 acc = make_float4(a0.x + a1.x + a2.x + a3.x, a0.y + a1.y + a2.y + a3.y,
                             a0.z + a1.z + a2.z + a3.z, a0.w + a1.w + a2.w + a3.w);

    float dd = g_dinv[node];
    float4 b4 = ((const float4*)bias)[l];
    float4 r = make_float4(fmaf(acc.x, dd, b4.x), fmaf(acc.y, dd, b4.y),
                           fmaf(acc.z, dd, b4.z), fmaf(acc.w, dd, b4.w));
    float4 sc = ((const float4*)g_bns[2])[l];
    float4 sh = ((const float4*)g_bnb[2])[l];
    r.x = fmaxf(fmaf(r.x, sc.x, sh.x), 0.f);
    r.y = fmaxf(fmaf(r.y, sc.y, sh.y), 0.f);
    r.z = fmaxf(fmaf(r.z, sc.z, sh.z), 0.f);
    r.w = fmaxf(fmaf(r.w, sc.w, sh.w), 0.f);

    int b = batch[node];
    float* p = g_pool + b * HID + l * 4;
    asm volatile("red.global.add.v4.f32 [%0], {%1, %2, %3, %4};"
                 :: "l"(p), "f"(r.x), "f"(r.y), "f"(r.z), "f"(r.w) : "memory");
    if (l == 0) atomicAdd(&g_cnt[b], 1.0f);
}

// ---------------- head: mean, concat pocket, 192->96 relu ->1 ---------------
__global__ void k_head(const float* __restrict__ cw1, const float* __restrict__ cb1,
                       const float* __restrict__ cw2, const float* __restrict__ cb2,
                       float* __restrict__ out) {
    __shared__ float emb[192];
    __shared__ float hid[96];
    int g = blockIdx.x;
    int j = threadIdx.x;
    float inv = 1.0f / fmaxf(g_cnt[g], 1.0f);
    for (int idx = j; idx < 192; idx += 96)
        emb[idx] = (idx < HID) ? g_pool[g * HID + idx] * inv : g_p[idx - HID];
    __syncthreads();
    float a = cb1[j];
    #pragma unroll 8
    for (int k = 0; k < 192; ++k) a = fmaf(emb[k], cw1[k * 96 + j], a);
    hid[j] = fmaxf(a, 0.0f) * cw2[j];
    __syncthreads();
    if (j == 0) {
        float s = cb2[0];
        #pragma unroll
        for (int k = 0; k < 96; ++k) s += hid[k];
        out[g] = s;
    }
}

// ---------------- launch --------------------------------------------------
extern "C" void kernel_launch(void* const* d_in, const int* in_sizes, int n_in,
                              void* d_out, int out_size) {
    const float* x      = (const float*)d_in[0];
    const int*   ei     = (const int*)  d_in[1];
    const int*   src    = ei;
    const int*   dst    = ei + N_EDGES;
    const int*   batch  = (const int*)  d_in[2];
    const float* pocket = (const float*)d_in[3];
    const float* W0 = (const float*)d_in[4];  const float* b0 = (const float*)d_in[5];
    const float* W1 = (const float*)d_in[6];  const float* b1 = (const float*)d_in[7];
    const float* W2 = (const float*)d_in[8];  const float* b2 = (const float*)d_in[9];
    const float* bn_gamma = (const float*)d_in[10];
    const float* bn_beta  = (const float*)d_in[11];
    const float* bn_mean  = (const float*)d_in[12];
    const float* bn_var   = (const float*)d_in[13];
    const float* pw1 = (const float*)d_in[14]; const float* pb1 = (const float*)d_in[15];
    const float* pw2 = (const float*)d_in[16]; const float* pb2 = (const float*)d_in[17];
    const float* cw1 = (const float*)d_in[18]; const float* cb1 = (const float*)d_in[19];
    const float* cw2 = (const float*)d_in[20]; const float* cb2 = (const float*)d_in[21];
    float* out = (float*)d_out;

    // prep + CSR build
    k_prep<<<1, 384>>>(bn_gamma, bn_beta, bn_mean, bn_var,
                       pocket, pw1, pb1, pw2, pb2);
    k_zeroW<<<NB_SCAN, 256>>>(W1, W2);
    k_count<<<(N_EDGES + 255) / 256, 256>>>(dst);
    k_scan1<<<NB_SCAN, 256>>>();
    k_scan2<<<1, 512>>>();
    k_scan3<<<NB_SCAN, 256>>>();
    k_fill<<<(N_EDGES + 255) / 256, 256>>>(src, dst);

    int tc_grid = (N_NODES + 127) / 128;
    int node_warp_grid = (N_NODES + 7) / 8;

    // layer 0: hl0' -> buf1
    k_gemm0<<<node_warp_grid, 256>>>(x, W0);
    k_gather<<<node_warp_grid, 256>>>(b0, 0, 1);   // buf1 -> buf0 (h0)
    // layer 1: hl1' -> buf1
    k_gemm128_tc<<<tc_grid, 256>>>(0);
    k_gather<<<node_warp_grid, 256>>>(b1, 1, 1);   // buf1 -> buf0 (h1)
    // layer 2: hl2' -> buf1
    k_gemm128_tc<<<tc_grid, 256>>>(1);
    // gather + BN2 + ReLU + pool, then head
    k_poolg<<<node_warp_grid, 256>>>(b2, batch);
    k_head<<<N_GRAPHS, 96>>>(cw1, cb1, cw2, cb2, out);
}

// round 15
// speedup vs baseline: 1.0815x; 1.0061x over previous
#include <cuda_runtime.h>
#include <cuda_bf16.h>
#include <mma.h>

using namespace nvcuda;

#define N_NODES  100000
#define N_EDGES  600000
#define N_GRAPHS 256
#define HID      128
#define IN_DIM   7
#define BN_EPS   1e-5f
#define NB_SCAN  ((N_NODES + 255) / 256)   // 391 scan blocks
#define N_PAD    (N_NODES + 128)           // row padding for full-tile wmma I/O

// ---------------- scratch (static device globals; no allocs allowed) --------
__device__ float g_buf0[N_PAD * HID];     // h buffer (gather out, post BN+ReLU)
__device__ float g_buf1[N_PAD * HID];     // hl buffer (GEMM out)
__device__ float g_Wc[2][HID * HID];      // tf32-rounded W1, W2
__device__ float g_dinv[N_NODES];         // rsqrt(deg+1)
__device__ float g_pool[N_GRAPHS * HID];
__device__ float g_cnt[N_GRAPHS];
__device__ float g_p[64];                 // pocket embedding
__device__ float g_bns[3][HID];           // BN scale  = gamma * rsqrt(var+eps)
__device__ float g_bnb[3][HID];           // BN shift  = beta - mean*scale
// CSR scratch
__device__ int   g_cnti[NB_SCAN * 256];   // per-node in-degree, then fill cursor
__device__ int   g_rowptr[N_NODES + 1];
__device__ int   g_ecol[N_EDGES];         // src node per CSR slot
__device__ int   g_bsum[512];             // per-block scan sums

// ---------------- merged prep: BN fold + pocket MLP (1 block, 384 thr) ------
__global__ void k_prep(const float* __restrict__ gamma, const float* __restrict__ beta,
                       const float* __restrict__ mean,  const float* __restrict__ var,
                       const float* __restrict__ pocket,
                       const float* __restrict__ pw1, const float* __restrict__ pb1,
                       const float* __restrict__ pw2, const float* __restrict__ pb2) {
    __shared__ float t[64];
    int j = threadIdx.x;
    if (j < 3 * HID) {
        float s = gamma[j] * rsqrtf(var[j] + BN_EPS);
        ((float*)g_bns)[j] = s;
        ((float*)g_bnb)[j] = beta[j] - mean[j] * s;
    }
    if (j < 64) {
        float a = pb1[j];
        #pragma unroll
        for (int k = 0; k < 28; ++k) a = fmaf(pocket[k], pw1[k * 64 + j], a);
        t[j] = fmaxf(a, 0.0f);
    }
    __syncthreads();
    if (j < 64) {
        float b = pb2[j];
        #pragma unroll
        for (int k = 0; k < 64; ++k) b = fmaf(t[k], pw2[k * 64 + j], b);
        g_p[j] = b;
    }
}

// zero counters/pool + tf32-round W1,W2 (merged elementwise prep)
__global__ void k_zeroW(const float* __restrict__ W1, const float* __restrict__ W2) {
    int i = blockIdx.x * blockDim.x + threadIdx.x;
    if (i < NB_SCAN * 256) g_cnti[i] = 0;
    if (i < N_GRAPHS * HID) g_pool[i] = 0.0f;
    if (i < N_GRAPHS) g_cnt[i] = 0.0f;
    if (i < HID * HID) {
        g_Wc[0][i] = wmma::__float_to_tf32(W1[i]);
        g_Wc[1][i] = wmma::__float_to_tf32(W2[i]);
    }
}

__global__ void k_count(const int* __restrict__ dst) {
    int i = blockIdx.x * blockDim.x + threadIdx.x;
    if (i < N_EDGES) atomicAdd(&g_cnti[dst[i]], 1);
}

// per-block inclusive scan of g_cnti -> g_rowptr (block-local), totals -> g_bsum
// also computes dinv = rsqrt(deg+1)
__global__ void k_scan1() {
    __shared__ int s[256];
    int t = threadIdx.x;
    int i = blockIdx.x * 256 + t;
    int v = (i < N_NODES) ? g_cnti[i] : 0;
    if (i < N_NODES) g_dinv[i] = rsqrtf((float)v + 1.0f);
    s[t] = v;
    __syncthreads();
    #pragma unroll
    for (int d = 1; d < 256; d <<= 1) {
        int x = (t >= d) ? s[t - d] : 0;
        __syncthreads();
        if (t >= d) s[t] += x;
        __syncthreads();
    }
    if (i <= N_NODES) g_rowptr[i] = s[t];     // inclusive, block-local
    if (t == 255) g_bsum[blockIdx.x] = s[255];
}

__global__ void k_scan2() {
    __shared__ int s[512];
    int t = threadIdx.x;
    int v = (t < NB_SCAN) ? g_bsum[t] : 0;
    s[t] = v;
    __syncthreads();
    #pragma unroll
    for (int d = 1; d < 512; d <<= 1) {
        int x = (t >= d) ? s[t - d] : 0;
        __syncthreads();
        if (t >= d) s[t] += x;
        __syncthreads();
    }
    if (t < NB_SCAN) g_bsum[t] = s[t] - v;    // exclusive block offset
}

__global__ void k_scan3() {
    int i = blockIdx.x * blockDim.x + threadIdx.x;
    if (i < N_NODES) {
        int incl = g_rowptr[i];
        int cnt  = g_cnti[i];
        g_rowptr[i] = g_bsum[i >> 8] + incl - cnt;   // global exclusive
        g_cnti[i] = 0;
    }
    if (i == 0) g_rowptr[N_NODES] = N_EDGES;
}

__global__ void k_fill(const int* __restrict__ src, const int* __restrict__ dst) {
    int e = blockIdx.x * blockDim.x + threadIdx.x;
    if (e < N_EDGES) {
        int d = dst[e];
        int pos = g_rowptr[d] + atomicAdd(&g_cnti[d], 1);
        g_ecol[pos] = src[e];
    }
}

// ---------------- layer 0 GEMM: x[N,7] @ W0[7,128] -> g_buf1 (hl only) ------
__global__ void k_gemm0(const float* __restrict__ x, const float* __restrict__ W0) {
    __shared__ float Ws[IN_DIM * HID];
    int tid = threadIdx.x;
    for (int i = tid; i < IN_DIM * HID; i += 256) Ws[i] = W0[i];
    __syncthreads();

    int node = blockIdx.x * 8 + (tid >> 5);
    int col  = (tid & 31) * 4;
    if (node >= N_NODES) return;

    float xr[IN_DIM];
    #pragma unroll
    for (int i = 0; i < IN_DIM; ++i) xr[i] = __ldg(&x[node * IN_DIM + i]);

    float4 acc = make_float4(0.f, 0.f, 0.f, 0.f);
    #pragma unroll
    for (int i = 0; i < IN_DIM; ++i) {
        float4 w = *(const float4*)&Ws[i * HID + col];
        acc.x = fmaf(xr[i], w.x, acc.x);
        acc.y = fmaf(xr[i], w.y, acc.y);
        acc.z = fmaf(xr[i], w.z, acc.z);
        acc.w = fmaf(xr[i], w.w, acc.w);
    }
    *(float4*)(g_buf1 + node * HID + col) = acc;
}

// ---------------- wmma tf32 GEMM (R12 form): raw copy + mma, direct store ---
__global__ void __launch_bounds__(256, 2)
k_gemm128_tc(int widx) {
    __shared__ float As[128][36];    // [m][k], ld=36
    __shared__ float Bs[32][132];    // [k][n], ld=132

    const float* Wc = g_Wc[widx];
    int tid = threadIdx.x;
    int wid = tid >> 5;
    int warp_m = wid >> 1, warp_n = wid & 1;
    int row0 = blockIdx.x * 128;

    wmma::fragment<wmma::accumulator, 16, 16, 8, float> acc[2][4];
    #pragma unroll
    for (int mt = 0; mt < 2; ++mt)
        #pragma unroll
        for (int nt = 0; nt < 4; ++nt) wmma::fill_fragment(acc[mt][nt], 0.0f);

    for (int k0 = 0; k0 < HID; k0 += 32) {
        #pragma unroll
        for (int i = 0; i < 4; ++i) {
            int f = tid + 256 * i;
            int r = f >> 5, c = (f & 31) * 4;
            *(float4*)&Bs[r][c] = *(const float4*)(Wc + (k0 + r) * HID + c);
        }
        #pragma unroll
        for (int i = 0; i < 4; ++i) {
            int f = tid + 256 * i;
            int r = f >> 3, c4 = (f & 7) * 4;
            *(float4*)&As[r][c4] = *(const float4*)(g_buf0 + (row0 + r) * HID + k0 + c4);
        }
        __syncthreads();

        #pragma unroll
        for (int kk = 0; kk < 4; ++kk) {
            wmma::fragment<wmma::matrix_a, 16, 16, 8, wmma::precision::tf32, wmma::row_major> fa[2];
            #pragma unroll
            for (int mt = 0; mt < 2; ++mt)
                wmma::load_matrix_sync(fa[mt], &As[warp_m * 32 + mt * 16][kk * 8], 36);
            #pragma unroll
            for (int nt = 0; nt < 4; ++nt) {
                wmma::fragment<wmma::matrix_b, 16, 16, 8, wmma::precision::tf32, wmma::row_major> fb;
                wmma::load_matrix_sync(fb, &Bs[kk * 8][warp_n * 64 + nt * 16], 132);
                wmma::mma_sync(acc[0][nt], fa[0], fb, acc[0][nt]);
                wmma::mma_sync(acc[1][nt], fa[1], fb, acc[1][nt]);
            }
        }
        __syncthreads();
    }

    #pragma unroll
    for (int mt = 0; mt < 2; ++mt) {
        int row = row0 + warp_m * 32 + mt * 16;
        #pragma unroll
        for (int nt = 0; nt < 4; ++nt) {
            int col = warp_n * 64 + nt * 16;
            wmma::store_matrix_sync(g_buf1 + row * HID + col, acc[mt][nt], HID, wmma::mem_row_major);
        }
    }
}

// ---------------- CSR gather (unroll x4, per-edge dinv fmaf) -----------------
// h = relu(BN[bn]( (Σ hl[s]*dinv[s] + hl[d]*dinv[d]) * dinv[d] + bias ));
// optional tf32 round. in = g_buf1, out = g_buf0.
__global__ void k_gather(const float* __restrict__ bias, int bn_idx, int do_round) {
    int node = blockIdx.x * 8 + (threadIdx.x >> 5);
    if (node >= N_NODES) return;
    int l = threadIdx.x & 31;

    const float4* in = (const float4*)g_buf1;
    int beg = g_rowptr[node];
    int end = g_rowptr[node + 1];

    float dd = g_dinv[node];
    float4 hv = in[node * 32 + l];
    float4 a0 = make_float4(hv.x * dd, hv.y * dd, hv.z * dd, hv.w * dd);  // self-loop
    float4 a1 = make_float4(0.f, 0.f, 0.f, 0.f);
    float4 a2 = make_float4(0.f, 0.f, 0.f, 0.f);
    float4 a3 = make_float4(0.f, 0.f, 0.f, 0.f);

    int e = beg;
    for (; e + 4 <= end; e += 4) {
        int s0 = g_ecol[e], s1 = g_ecol[e + 1], s2 = g_ecol[e + 2], s3 = g_ecol[e + 3];
        float d0 = g_dinv[s0], d1 = g_dinv[s1], d2 = g_dinv[s2], d3 = g_dinv[s3];
        float4 v0 = in[s0 * 32 + l];
        float4 v1 = in[s1 * 32 + l];
        float4 v2 = in[s2 * 32 + l];
        float4 v3 = in[s3 * 32 + l];
        a0.x = fmaf(v0.x, d0, a0.x); a0.y = fmaf(v0.y, d0, a0.y);
        a0.z = fmaf(v0.z, d0, a0.z); a0.w = fmaf(v0.w, d0, a0.w);
        a1.x = fmaf(v1.x, d1, a1.x); a1.y = fmaf(v1.y, d1, a1.y);
        a1.z = fmaf(v1.z, d1, a1.z); a1.w = fmaf(v1.w, d1, a1.w);
        a2.x = fmaf(v2.x, d2, a2.x); a2.y = fmaf(v2.y, d2, a2.y);
        a2.z = fmaf(v2.z, d2, a2.z); a2.w = fmaf(v2.w, d2, a2.w);
        a3.x = fmaf(v3.x, d3, a3.x); a3.y = fmaf(v3.y, d3, a3.y);
        a3.z = fmaf(v3.z, d3, a3.z); a3.w = fmaf(v3.w, d3, a3.w);
    }
    for (; e < end; ++e) {
        int s = g_ecol[e];
        float ds = g_dinv[s];
        float4 v = in[s * 32 + l];
        a0.x = fmaf(v.x, ds, a0.x); a0.y = fmaf(v.y, ds, a0.y);
        a0.z = fmaf(v.z, ds, a0.z); a0.w = fmaf(v.w, ds, a0.w);
    }
    float4 acc = make_float4(a0.x + a1.x + a2.x + a3.x, a0.y + a1.y + a2.y + a3.y,
                             a0.z + a1.z + a2.z + a3.z, a0.w + a1.w + a2.w + a3.w);

    float4 b4 = ((const float4*)bias)[l];
    float4 r = make_float4(fmaf(acc.x, dd, b4.x), fmaf(acc.y, dd, b4.y),
                           fmaf(acc.z, dd, b4.z), fmaf(acc.w, dd, b4.w));
    float4 sc = ((const float4*)g_bns[bn_idx])[l];
    float4 sh = ((const float4*)g_bnb[bn_idx])[l];
    r.x = fmaxf(fmaf(r.x, sc.x, sh.x), 0.f);
    r.y = fmaxf(fmaf(r.y, sc.y, sh.y), 0.f);
    r.z = fmaxf(fmaf(r.z, sc.z, sh.z), 0.f);
    r.w = fmaxf(fmaf(r.w, sc.w, sh.w), 0.f);
    if (do_round) {
        r.x = wmma::__float_to_tf32(r.x);
        r.y = wmma::__float_to_tf32(r.y);
        r.z = wmma::__float_to_tf32(r.z);
        r.w = wmma::__float_to_tf32(r.w);
    }
    ((float4*)g_buf0)[node * 32 + l] = r;
}

// ---------------- fused gather + BN2 + ReLU + pooling -----------------------
__global__ void k_poolg(const float* __restrict__ bias, const int* __restrict__ batch) {
    int node = blockIdx.x * 8 + (threadIdx.x >> 5);
    if (node >= N_NODES) return;
    int l = threadIdx.x & 31;

    const float4* in = (const float4*)g_buf1;
    int beg = g_rowptr[node];
    int end = g_rowptr[node + 1];

    float dd = g_dinv[node];
    float4 hv = in[node * 32 + l];
    float4 a0 = make_float4(hv.x * dd, hv.y * dd, hv.z * dd, hv.w * dd);
    float4 a1 = make_float4(0.f, 0.f, 0.f, 0.f);
    float4 a2 = make_float4(0.f, 0.f, 0.f, 0.f);
    float4 a3 = make_float4(0.f, 0.f, 0.f, 0.f);

    int e = beg;
    for (; e + 4 <= end; e += 4) {
        int s0 = g_ecol[e], s1 = g_ecol[e + 1], s2 = g_ecol[e + 2], s3 = g_ecol[e + 3];
        float d0 = g_dinv[s0], d1 = g_dinv[s1], d2 = g_dinv[s2], d3 = g_dinv[s3];
        float4 v0 = in[s0 * 32 + l];
        float4 v1 = in[s1 * 32 + l];
        float4 v2 = in[s2 * 32 + l];
        float4 v3 = in[s3 * 32 + l];
        a0.x = fmaf(v0.x, d0, a0.x); a0.y = fmaf(v0.y, d0, a0.y);
        a0.z = fmaf(v0.z, d0, a0.z); a0.w = fmaf(v0.w, d0, a0.w);
        a1.x = fmaf(v1.x, d1, a1.x); a1.y = fmaf(v1.y, d1, a1.y);
        a1.z = fmaf(v1.z, d1, a1.z); a1.w = fmaf(v1.w, d1, a1.w);
        a2.x = fmaf(v2.x, d2, a2.x); a2.y = fmaf(v2.y, d2, a2.y);
        a2.z = fmaf(v2.z, d2, a2.z); a2.w = fmaf(v2.w, d2, a2.w);
        a3.x = fmaf(v3.x, d3, a3.x); a3.y = fmaf(v3.y, d3, a3.y);
        a3.z = fmaf(v3.z, d3, a3.z); a3.w = fmaf(v3.w, d3, a3.w);
    }
    for (; e < end; ++e) {
        int s = g_ecol[e];
        float ds = g_dinv[s];
        float4 v = in[s * 32 + l];
        a0.x = fmaf(v.x, ds, a0.x); a0.y = fmaf(v.y, ds, a0.y);
        a0.z = fmaf(v.z, ds, a0.z); a0.w = fmaf(v.w, ds, a0.w);
    }
    float4 acc = make_float4(a0.x + a1.x + a2.x + a3.x, a0.y + a1.y + a2.y + a3.y,
                             a0.z + a1.z + a2.z + a3.z, a0.w + a1.w + a2.w + a3.w);

    float4 b4 = ((const float4*)bias)[l];
    float4 r = make_float4(fmaf(acc.x, dd, b4.x), fmaf(acc.y, dd, b4.y),
                           fmaf(acc.z, dd, b4.z), fmaf(acc.w, dd, b4.w));
    float4 sc = ((const float4*)g_bns[2])[l];
    float4 sh = ((const float4*)g_bnb[2])[l];
    r.x = fmaxf(fmaf(r.x, sc.x, sh.x), 0.f);
    r.y = fmaxf(fmaf(r.y, sc.y, sh.y), 0.f);
    r.z = fmaxf(fmaf(r.z, sc.z, sh.z), 0.f);
    r.w = fmaxf(fmaf(r.w, sc.w, sh.w), 0.f);

    int b = batch[node];
    float* p = g_pool + b * HID + l * 4;
    asm volatile("red.global.add.v4.f32 [%0], {%1, %2, %3, %4};"
                 :: "l"(p), "f"(r.x), "f"(r.y), "f"(r.z), "f"(r.w) : "memory");
    if (l == 0) atomicAdd(&g_cnt[b], 1.0f);
}

// ---------------- head: mean, concat pocket, 192->96 relu ->1 ---------------
__global__ void k_head(const float* __restrict__ cw1, const float* __restrict__ cb1,
                       const float* __restrict__ cw2, const float* __restrict__ cb2,
                       float* __restrict__ out) {
    __shared__ float emb[192];
    __shared__ float hid[96];
    int g = blockIdx.x;
    int j = threadIdx.x;
    float inv = 1.0f / fmaxf(g_cnt[g], 1.0f);
    for (int idx = j; idx < 192; idx += 96)
        emb[idx] = (idx < HID) ? g_pool[g * HID + idx] * inv : g_p[idx - HID];
    __syncthreads();
    float a = cb1[j];
    #pragma unroll 8
    for (int k = 0; k < 192; ++k) a = fmaf(emb[k], cw1[k * 96 + j], a);
    hid[j] = fmaxf(a, 0.0f) * cw2[j];
    __syncthreads();
    if (j == 0) {
        float s = cb2[0];
        #pragma unroll
        for (int k = 0; k < 96; ++k) s += hid[k];
        out[g] = s;
    }
}

// ---------------- launch --------------------------------------------------
extern "C" void kernel_launch(void* const* d_in, const int* in_sizes, int n_in,
                              void* d_out, int out_size) {
    const float* x      = (const float*)d_in[0];
    const int*   ei     = (const int*)  d_in[1];
    const int*   src    = ei;
    const int*   dst    = ei + N_EDGES;
    const int*   batch  = (const int*)  d_in[2];
    const float* pocket = (const float*)d_in[3];
    const float* W0 = (const float*)d_in[4];  const float* b0 = (const float*)d_in[5];
    const float* W1 = (const float*)d_in[6];  const float* b1 = (const float*)d_in[7];
    const float* W2 = (const float*)d_in[8];  const float* b2 = (const float*)d_in[9];
    const float* bn_gamma = (const float*)d_in[10];
    const float* bn_beta  = (const float*)d_in[11];
    const float* bn_mean  = (const float*)d_in[12];
    const float* bn_var   = (const float*)d_in[13];
    const float* pw1 = (const float*)d_in[14]; const float* pb1 = (const float*)d_in[15];
    const float* pw2 = (const float*)d_in[16]; const float* pb2 = (const float*)d_in[17];
    const float* cw1 = (const float*)d_in[18]; const float* cb1 = (const float*)d_in[19];
    const float* cw2 = (const float*)d_in[20]; const float* cb2 = (const float*)d_in[21];
    float* out = (float*)d_out;

    // prep + CSR build
    k_prep<<<1, 384>>>(bn_gamma, bn_beta, bn_mean, bn_var,
                       pocket, pw1, pb1, pw2, pb2);
    k_zeroW<<<NB_SCAN, 256>>>(W1, W2);
    k_count<<<(N_EDGES + 255) / 256, 256>>>(dst);
    k_scan1<<<NB_SCAN, 256>>>();
    k_scan2<<<1, 512>>>();
    k_scan3<<<NB_SCAN, 256>>>();
    k_fill<<<(N_EDGES + 255) / 256, 256>>>(src, dst);

    int tc_grid = (N_NODES + 127) / 128;
    int node_warp_grid = (N_NODES + 7) / 8;

    // layer 0: hl0 -> buf1
    k_gemm0<<<node_warp_grid, 256>>>(x, W0);
    k_gather<<<node_warp_grid, 256>>>(b0, 0, 1);   // buf1 -> buf0 (h0, tf32)
    // layer 1: hl1 -> buf1
    k_gemm128_tc<<<tc_grid, 256>>>(0);
    k_gather<<<node_warp_grid, 256>>>(b1, 1, 1);   // buf1 -> buf0 (h1, tf32)
    // layer 2: hl2 -> buf1
    k_gemm128_tc<<<tc_grid, 256>>>(1);
    // gather + BN2 + ReLU + pool, then head
    k_poolg<<<node_warp_grid, 256>>>(b2, batch);
    k_head<<<N_GRAPHS, 96>>>(cw1, cb1, cw2, cb2, out);
}

// round 16
// speedup vs baseline: 1.1709x; 1.0827x over previous
#include <cuda_runtime.h>
#include <cuda_bf16.h>
#include <mma.h>

using namespace nvcuda;

#define N_NODES  100000
#define N_EDGES  600000
#define N_GRAPHS 256
#define HID      128
#define IN_DIM   7
#define BN_EPS   1e-5f
#define NB_SCAN  ((N_NODES + 255) / 256)   // 391 scan blocks
#define N_PAD    (N_NODES + 128)           // row padding for full-tile wmma I/O

// ---------------- scratch (static device globals; no allocs allowed) --------
__device__ float g_buf0[N_PAD * HID];     // h buffer (gather out, post BN+ReLU)
__device__ float g_buf1[N_PAD * HID];     // hl buffer (GEMM out)
__device__ float g_Wc[2][HID * HID];      // tf32-rounded W1, W2
__device__ float g_dinv[N_NODES];         // rsqrt(deg+1)
__device__ float g_pool[N_GRAPHS * HID];
__device__ float g_cnt[N_GRAPHS];
__device__ float g_p[64];                 // pocket embedding
__device__ float g_bns[3][HID];           // BN scale  = gamma * rsqrt(var+eps)
__device__ float g_bnb[3][HID];           // BN shift  = beta - mean*scale
// CSR scratch
__device__ int   g_cnti[NB_SCAN * 256];   // per-node in-degree, then fill cursor
__device__ int   g_rowptr[N_NODES + 1];
__device__ int   g_ecol[N_EDGES];         // src node per CSR slot
__device__ int   g_bsum[512];             // per-block scan sums

// ---------------- merged prep: BN fold + pocket MLP (1 block, 384 thr) ------
__global__ void k_prep(const float* __restrict__ gamma, const float* __restrict__ beta,
                       const float* __restrict__ mean,  const float* __restrict__ var,
                       const float* __restrict__ pocket,
                       const float* __restrict__ pw1, const float* __restrict__ pb1,
                       const float* __restrict__ pw2, const float* __restrict__ pb2) {
    __shared__ float t[64];
    int j = threadIdx.x;
    if (j < 3 * HID) {
        float s = gamma[j] * rsqrtf(var[j] + BN_EPS);
        ((float*)g_bns)[j] = s;
        ((float*)g_bnb)[j] = beta[j] - mean[j] * s;
    }
    if (j < 64) {
        float a = pb1[j];
        #pragma unroll
        for (int k = 0; k < 28; ++k) a = fmaf(pocket[k], pw1[k * 64 + j], a);
        t[j] = fmaxf(a, 0.0f);
    }
    __syncthreads();
    if (j < 64) {
        float b = pb2[j];
        #pragma unroll
        for (int k = 0; k < 64; ++k) b = fmaf(t[k], pw2[k * 64 + j], b);
        g_p[j] = b;
    }
}

// zero counters/pool + tf32-round W1,W2 (merged elementwise prep)
__global__ void k_zeroW(const float* __restrict__ W1, const float* __restrict__ W2) {
    int i = blockIdx.x * blockDim.x + threadIdx.x;
    if (i < NB_SCAN * 256) g_cnti[i] = 0;
    if (i < N_GRAPHS * HID) g_pool[i] = 0.0f;
    if (i < N_GRAPHS) g_cnt[i] = 0.0f;
    if (i < HID * HID) {
        g_Wc[0][i] = wmma::__float_to_tf32(W1[i]);
        g_Wc[1][i] = wmma::__float_to_tf32(W2[i]);
    }
}

__global__ void k_count(const int* __restrict__ dst) {
    int i = blockIdx.x * blockDim.x + threadIdx.x;
    if (i < N_EDGES) atomicAdd(&g_cnti[dst[i]], 1);
}

// per-block inclusive scan of g_cnti -> g_rowptr (block-local), totals -> g_bsum
// also computes dinv = rsqrt(deg+1)
__global__ void k_scan1() {
    __shared__ int s[256];
    int t = threadIdx.x;
    int i = blockIdx.x * 256 + t;
    int v = (i < N_NODES) ? g_cnti[i] : 0;
    if (i < N_NODES) g_dinv[i] = rsqrtf((float)v + 1.0f);
    s[t] = v;
    __syncthreads();
    #pragma unroll
    for (int d = 1; d < 256; d <<= 1) {
        int x = (t >= d) ? s[t - d] : 0;
        __syncthreads();
        if (t >= d) s[t] += x;
        __syncthreads();
    }
    if (i <= N_NODES) g_rowptr[i] = s[t];     // inclusive, block-local
    if (t == 255) g_bsum[blockIdx.x] = s[255];
}

__global__ void k_scan2() {
    __shared__ int s[512];
    int t = threadIdx.x;
    int v = (t < NB_SCAN) ? g_bsum[t] : 0;
    s[t] = v;
    __syncthreads();
    #pragma unroll
    for (int d = 1; d < 512; d <<= 1) {
        int x = (t >= d) ? s[t - d] : 0;
        __syncthreads();
        if (t >= d) s[t] += x;
        __syncthreads();
    }
    if (t < NB_SCAN) g_bsum[t] = s[t] - v;    // exclusive block offset
}

__global__ void k_scan3() {
    int i = blockIdx.x * blockDim.x + threadIdx.x;
    if (i < N_NODES) {
        int incl = g_rowptr[i];
        int cnt  = g_cnti[i];
        g_rowptr[i] = g_bsum[i >> 8] + incl - cnt;   // global exclusive
        g_cnti[i] = 0;
    }
    if (i == 0) g_rowptr[N_NODES] = N_EDGES;
}

__global__ void k_fill(const int* __restrict__ src, const int* __restrict__ dst) {
    int e = blockIdx.x * blockDim.x + threadIdx.x;
    if (e < N_EDGES) {
        int d = dst[e];
        int pos = g_rowptr[d] + atomicAdd(&g_cnti[d], 1);
        g_ecol[pos] = src[e];
    }
}

// ---------------- layer 0 GEMM: x[N,7] @ W0[7,128] -> g_buf1 (hl only) ------
__global__ void k_gemm0(const float* __restrict__ x, const float* __restrict__ W0) {
    __shared__ float Ws[IN_DIM * HID];
    int tid = threadIdx.x;
    for (int i = tid; i < IN_DIM * HID; i += 256) Ws[i] = W0[i];
    __syncthreads();

    int node = blockIdx.x * 8 + (tid >> 5);
    int col  = (tid & 31) * 4;
    if (node >= N_NODES) return;

    float xr[IN_DIM];
    #pragma unroll
    for (int i = 0; i < IN_DIM; ++i) xr[i] = __ldg(&x[node * IN_DIM + i]);

    float4 acc = make_float4(0.f, 0.f, 0.f, 0.f);
    #pragma unroll
    for (int i = 0; i < IN_DIM; ++i) {
        float4 w = *(const float4*)&Ws[i * HID + col];
        acc.x = fmaf(xr[i], w.x, acc.x);
        acc.y = fmaf(xr[i], w.y, acc.y);
        acc.z = fmaf(xr[i], w.z, acc.z);
        acc.w = fmaf(xr[i], w.w, acc.w);
    }
    *(float4*)(g_buf1 + node * HID + col) = acc;
}

// ---------------- wmma tf32 GEMM (R12 form): raw copy + mma, direct store ---
__global__ void __launch_bounds__(256, 2)
k_gemm128_tc(int widx) {
    __shared__ float As[128][36];    // [m][k], ld=36
    __shared__ float Bs[32][132];    // [k][n], ld=132

    const float* Wc = g_Wc[widx];
    int tid = threadIdx.x;
    int wid = tid >> 5;
    int warp_m = wid >> 1, warp_n = wid & 1;
    int row0 = blockIdx.x * 128;

    wmma::fragment<wmma::accumulator, 16, 16, 8, float> acc[2][4];
    #pragma unroll
    for (int mt = 0; mt < 2; ++mt)
        #pragma unroll
        for (int nt = 0; nt < 4; ++nt) wmma::fill_fragment(acc[mt][nt], 0.0f);

    for (int k0 = 0; k0 < HID; k0 += 32) {
        #pragma unroll
        for (int i = 0; i < 4; ++i) {
            int f = tid + 256 * i;
            int r = f >> 5, c = (f & 31) * 4;
            *(float4*)&Bs[r][c] = *(const float4*)(Wc + (k0 + r) * HID + c);
        }
        #pragma unroll
        for (int i = 0; i < 4; ++i) {
            int f = tid + 256 * i;
            int r = f >> 3, c4 = (f & 7) * 4;
            *(float4*)&As[r][c4] = *(const float4*)(g_buf0 + (row0 + r) * HID + k0 + c4);
        }
        __syncthreads();

        #pragma unroll
        for (int kk = 0; kk < 4; ++kk) {
            wmma::fragment<wmma::matrix_a, 16, 16, 8, wmma::precision::tf32, wmma::row_major> fa[2];
            #pragma unroll
            for (int mt = 0; mt < 2; ++mt)
                wmma::load_matrix_sync(fa[mt], &As[warp_m * 32 + mt * 16][kk * 8], 36);
            #pragma unroll
            for (int nt = 0; nt < 4; ++nt) {
                wmma::fragment<wmma::matrix_b, 16, 16, 8, wmma::precision::tf32, wmma::row_major> fb;
                wmma::load_matrix_sync(fb, &Bs[kk * 8][warp_n * 64 + nt * 16], 132);
                wmma::mma_sync(acc[0][nt], fa[0], fb, acc[0][nt]);
                wmma::mma_sync(acc[1][nt], fa[1], fb, acc[1][nt]);
            }
        }
        __syncthreads();
    }

    #pragma unroll
    for (int mt = 0; mt < 2; ++mt) {
        int row = row0 + warp_m * 32 + mt * 16;
        #pragma unroll
        for (int nt = 0; nt < 4; ++nt) {
            int col = warp_n * 64 + nt * 16;
            wmma::store_matrix_sync(g_buf1 + row * HID + col, acc[mt][nt], HID, wmma::mem_row_major);
        }
    }
}

// ---------------- CSR gather (R12 simple loop) -------------------------------
// h = relu(BN[bn]( (Σ hl[s]*dinv[s] + hl[d]*dinv[d]) * dinv[d] + bias ));
// optional tf32 round. in = g_buf1, out = g_buf0.
__global__ void k_gather(const float* __restrict__ bias, int bn_idx, int do_round) {
    int node = blockIdx.x * 8 + (threadIdx.x >> 5);
    if (node >= N_NODES) return;
    int l = threadIdx.x & 31;

    const float4* in = (const float4*)g_buf1;
    int beg = g_rowptr[node];
    int end = g_rowptr[node + 1];

    float4 acc = make_float4(0.f, 0.f, 0.f, 0.f);
    for (int e = beg; e < end; ++e) {
        int s = g_ecol[e];                       // warp-uniform -> broadcast
        float ds = g_dinv[s];
        float4 v = in[s * 32 + l];
        acc.x = fmaf(v.x, ds, acc.x);
        acc.y = fmaf(v.y, ds, acc.y);
        acc.z = fmaf(v.z, ds, acc.z);
        acc.w = fmaf(v.w, ds, acc.w);
    }
    float dd = g_dinv[node];
    float4 hv = in[node * 32 + l];               // self-loop term
    acc.x = fmaf(hv.x, dd, acc.x);
    acc.y = fmaf(hv.y, dd, acc.y);
    acc.z = fmaf(hv.z, dd, acc.z);
    acc.w = fmaf(hv.w, dd, acc.w);
    float4 b4 = ((const float4*)bias)[l];
    float4 r = make_float4(fmaf(acc.x, dd, b4.x), fmaf(acc.y, dd, b4.y),
                           fmaf(acc.z, dd, b4.z), fmaf(acc.w, dd, b4.w));
    float4 sc = ((const float4*)g_bns[bn_idx])[l];
    float4 sh = ((const float4*)g_bnb[bn_idx])[l];
    r.x = fmaxf(fmaf(r.x, sc.x, sh.x), 0.f);
    r.y = fmaxf(fmaf(r.y, sc.y, sh.y), 0.f);
    r.z = fmaxf(fmaf(r.z, sc.z, sh.z), 0.f);
    r.w = fmaxf(fmaf(r.w, sc.w, sh.w), 0.f);
    if (do_round) {
        r.x = wmma::__float_to_tf32(r.x);
        r.y = wmma::__float_to_tf32(r.y);
        r.z = wmma::__float_to_tf32(r.z);
        r.w = wmma::__float_to_tf32(r.w);
    }
    ((float4*)g_buf0)[node * 32 + l] = r;
}

// ---------------- fused gather + BN2 + ReLU + pooling (simple loop) ----------
__global__ void k_poolg(const float* __restrict__ bias, const int* __restrict__ batch) {
    int node = blockIdx.x * 8 + (threadIdx.x >> 5);
    if (node >= N_NODES) return;
    int l = threadIdx.x & 31;

    const float4* in = (const float4*)g_buf1;
    int beg = g_rowptr[node];
    int end = g_rowptr[node + 1];

    float4 acc = make_float4(0.f, 0.f, 0.f, 0.f);
    for (int e = beg; e < end; ++e) {
        int s = g_ecol[e];
        float ds = g_dinv[s];
        float4 v = in[s * 32 + l];
        acc.x = fmaf(v.x, ds, acc.x);
        acc.y = fmaf(v.y, ds, acc.y);
        acc.z = fmaf(v.z, ds, acc.z);
        acc.w = fmaf(v.w, ds, acc.w);
    }
    float dd = g_dinv[node];
    float4 hv = in[node * 32 + l];
    acc.x = fmaf(hv.x, dd, acc.x);
    acc.y = fmaf(hv.y, dd, acc.y);
    acc.z = fmaf(hv.z, dd, acc.z);
    acc.w = fmaf(hv.w, dd, acc.w);
    float4 b4 = ((const float4*)bias)[l];
    float4 r = make_float4(fmaf(acc.x, dd, b4.x), fmaf(acc.y, dd, b4.y),
                           fmaf(acc.z, dd, b4.z), fmaf(acc.w, dd, b4.w));
    float4 sc = ((const float4*)g_bns[2])[l];
    float4 sh = ((const float4*)g_bnb[2])[l];
    r.x = fmaxf(fmaf(r.x, sc.x, sh.x), 0.f);
    r.y = fmaxf(fmaf(r.y, sc.y, sh.y), 0.f);
    r.z = fmaxf(fmaf(r.z, sc.z, sh.z), 0.f);
    r.w = fmaxf(fmaf(r.w, sc.w, sh.w), 0.f);

    int b = batch[node];
    float* p = g_pool + b * HID + l * 4;
    asm volatile("red.global.add.v4.f32 [%0], {%1, %2, %3, %4};"
                 :: "l"(p), "f"(r.x), "f"(r.y), "f"(r.z), "f"(r.w) : "memory");
    if (l == 0) atomicAdd(&g_cnt[b], 1.0f);
}

// ---------------- head: mean, concat pocket, 192->96 relu ->1 ---------------
__global__ void k_head(const float* __restrict__ cw1, const float* __restrict__ cb1,
                       const float* __restrict__ cw2, const float* __restrict__ cb2,
                       float* __restrict__ out) {
    __shared__ float emb[192];
    __shared__ float hid[96];
    int g = blockIdx.x;
    int j = threadIdx.x;
    float inv = 1.0f / fmaxf(g_cnt[g], 1.0f);
    for (int idx = j; idx < 192; idx += 96)
        emb[idx] = (idx < HID) ? g_pool[g * HID + idx] * inv : g_p[idx - HID];
    __syncthreads();
    float a = cb1[j];
    #pragma unroll 8
    for (int k = 0; k < 192; ++k) a = fmaf(emb[k], cw1[k * 96 + j], a);
    hid[j] = fmaxf(a, 0.0f) * cw2[j];
    __syncthreads();
    if (j == 0) {
        float s = cb2[0];
        #pragma unroll
        for (int k = 0; k < 96; ++k) s += hid[k];
        out[g] = s;
    }
}

// ---------------- launch --------------------------------------------------
extern "C" void kernel_launch(void* const* d_in, const int* in_sizes, int n_in,
                              void* d_out, int out_size) {
    const float* x      = (const float*)d_in[0];
    const int*   ei     = (const int*)  d_in[1];
    const int*   src    = ei;
    const int*   dst    = ei + N_EDGES;
    const int*   batch  = (const int*)  d_in[2];
    const float* pocket = (const float*)d_in[3];
    const float* W0 = (const float*)d_in[4];  const float* b0 = (const float*)d_in[5];
    const float* W1 = (const float*)d_in[6];  const float* b1 = (const float*)d_in[7];
    const float* W2 = (const float*)d_in[8];  const float* b2 = (const float*)d_in[9];
    const float* bn_gamma = (const float*)d_in[10];
    const float* bn_beta  = (const float*)d_in[11];
    const float* bn_mean  = (const float*)d_in[12];
    const float* bn_var   = (const float*)d_in[13];
    const float* pw1 = (const float*)d_in[14]; const float* pb1 = (const float*)d_in[15];
    const float* pw2 = (const float*)d_in[16]; const float* pb2 = (const float*)d_in[17];
    const float* cw1 = (const float*)d_in[18]; const float* cb1 = (const float*)d_in[19];
    const float* cw2 = (const float*)d_in[20]; const float* cb2 = (const float*)d_in[21];
    float* out = (float*)d_out;

    // prep + CSR build
    k_prep<<<1, 384>>>(bn_gamma, bn_beta, bn_mean, bn_var,
                       pocket, pw1, pb1, pw2, pb2);
    k_zeroW<<<NB_SCAN, 256>>>(W1, W2);
    k_count<<<(N_EDGES + 255) / 256, 256>>>(dst);
    k_scan1<<<NB_SCAN, 256>>>();
    k_scan2<<<1, 512>>>();
    k_scan3<<<NB_SCAN, 256>>>();
    k_fill<<<(N_EDGES + 255) / 256, 256>>>(src, dst);

    int tc_grid = (N_NODES + 127) / 128;
    int node_warp_grid = (N_NODES + 7) / 8;

    // layer 0: hl0 -> buf1
    k_gemm0<<<node_warp_grid, 256>>>(x, W0);
    k_gather<<<node_warp_grid, 256>>>(b0, 0, 1);   // buf1 -> buf0 (h0, tf32)
    // layer 1: hl1 -> buf1
    k_gemm128_tc<<<tc_grid, 256>>>(0);
    k_gather<<<node_warp_grid, 256>>>(b1, 1, 1);   // buf1 -> buf0 (h1, tf32)
    // layer 2: hl2 -> buf1
    k_gemm128_tc<<<tc_grid, 256>>>(1);
    // gather + BN2 + ReLU + pool, then head
    k_poolg<<<node_warp_grid, 256>>>(b2, batch);
    k_head<<<N_GRAPHS, 96>>>(cw1, cb1, cw2, cb2, out);
}